// round 1
// baseline (speedup 1.0000x reference)
#include <cuda_runtime.h>

#define B_   16
#define N_   16384
#define C_   288
#define S_   256
#define KS   16
#define CIN0 291
#define SK   4096
#define WT_STRIDE (292*288)

// ---------------- scratch (device globals; allocation-free) ----------------
__device__ float g_newxyz[B_*S_*3];
__device__ int   g_idx[B_*S_*KS];
__device__ float g_h0[(long)B_*CIN0*SK];   // 76 MB
__device__ float g_h1[(long)B_*C_*SK];     // 75 MB
__device__ float g_h2[(long)B_*C_*SK];     // 75 MB
__device__ float g_Wt[3*WT_STRIDE];        // transposed weights

// ---------------- FPS: 1 CTA per batch, xyz in SMEM, exact math ----------------
extern __shared__ float fps_sm[];
__global__ void __launch_bounds__(1024) fps_kernel(const float* __restrict__ xyz,
                                                   float* __restrict__ out_xyz,
                                                   float* __restrict__ out_inds)
{
    float* sx = fps_sm;
    float* sy = fps_sm + N_;
    float* sz = fps_sm + 2*N_;
    __shared__ float r_d[32];
    __shared__ int   r_i[32];
    __shared__ float s_c[3];
    __shared__ int   s_ci;

    int b = blockIdx.x, tid = threadIdx.x;
    const float* xb = xyz + (long)b*N_*3;
    for (int i = tid; i < N_; i += 1024) {
        sx[i] = xb[3*i];
        sy[i] = xb[3*i+1];
        sz[i] = xb[3*i+2];
    }
    float dist[16];
#pragma unroll
    for (int j = 0; j < 16; j++) dist[j] = 1e10f;
    if (tid == 0) s_ci = 0;
    __syncthreads();
    if (tid == 0) { s_c[0] = sx[0]; s_c[1] = sy[0]; s_c[2] = sz[0]; }
    __syncthreads();

    int lane = tid & 31, wid = tid >> 5;
    for (int t = 0; t < S_; t++) {
        float cx = s_c[0], cy = s_c[1], cz = s_c[2];
        if (tid == 0) {
            int ci = s_ci;
            out_inds[b*S_ + t] = (float)ci;
            out_xyz[(b*S_ + t)*3 + 0] = cx;
            out_xyz[(b*S_ + t)*3 + 1] = cy;
            out_xyz[(b*S_ + t)*3 + 2] = cz;
            g_newxyz[(b*S_ + t)*3 + 0] = cx;
            g_newxyz[(b*S_ + t)*3 + 1] = cy;
            g_newxyz[(b*S_ + t)*3 + 2] = cz;
        }
        float bd = -1.0f; int bi = 0;
#pragma unroll
        for (int j = 0; j < 16; j++) {
            int p = j*1024 + tid;
            float dx = sx[p] - cx, dy = sy[p] - cy, dz = sz[p] - cz;
            // exact ((dx*dx + dy*dy) + dz*dz), no FMA contraction
            float d = __fadd_rn(__fadd_rn(__fmul_rn(dx,dx), __fmul_rn(dy,dy)), __fmul_rn(dz,dz));
            float dm = fminf(dist[j], d);
            dist[j] = dm;
            if (dm > bd) { bd = dm; bi = p; }   // strict > keeps lowest p per thread
        }
#pragma unroll
        for (int off = 16; off; off >>= 1) {
            float od = __shfl_down_sync(0xffffffffu, bd, off);
            int   oi = __shfl_down_sync(0xffffffffu, bi, off);
            if (od > bd || (od == bd && oi < bi)) { bd = od; bi = oi; }
        }
        if (lane == 0) { r_d[wid] = bd; r_i[wid] = bi; }
        __syncthreads();
        if (wid == 0) {
            bd = r_d[lane]; bi = r_i[lane];
#pragma unroll
            for (int off = 16; off; off >>= 1) {
                float od = __shfl_down_sync(0xffffffffu, bd, off);
                int   oi = __shfl_down_sync(0xffffffffu, bi, off);
                if (od > bd || (od == bd && oi < bi)) { bd = od; bi = oi; }
            }
            if (lane == 0) { s_ci = bi; s_c[0] = sx[bi]; s_c[1] = sy[bi]; s_c[2] = sz[bi]; }
        }
        __syncthreads();
    }
}

// ---------------- ball query: 1 warp per center, index-ordered first-16 ----------------
__global__ void ballq_kernel(const float* __restrict__ xyz)
{
    int gw   = (blockIdx.x * blockDim.x + threadIdx.x) >> 5;   // 0..4095
    int lane = threadIdx.x & 31;
    int b = gw >> 8, s = gw & 255;
    const float* xb = xyz + (long)b*N_*3;
    float cx = g_newxyz[(b*S_+s)*3 + 0];
    float cy = g_newxyz[(b*S_+s)*3 + 1];
    float cz = g_newxyz[(b*S_+s)*3 + 2];
    int* out = g_idx + (b*S_+s)*KS;
    int count = 0, first = -1;
    for (int base = 0; base < N_; base += 32) {
        int p = base + lane;
        float dx = xb[3*p] - cx, dy = xb[3*p+1] - cy, dz = xb[3*p+2] - cz;
        float d = __fadd_rn(__fadd_rn(__fmul_rn(dx,dx), __fmul_rn(dy,dy)), __fmul_rn(dz,dz));
        bool in = d < 0.09f;
        unsigned mask = __ballot_sync(0xffffffffu, in);
        if (first < 0 && mask) first = base + __ffs(mask) - 1;
        if (in) {
            int slot = count + __popc(mask & ((1u << lane) - 1u));
            if (slot < KS) out[slot] = p;
        }
        count += __popc(mask);
        if (count >= KS) break;
    }
    if (lane < KS && lane >= count) out[lane] = first;
}

// ---------------- gather + concat -> h0 [b][c][s*16+k] ----------------
__global__ void gather_kernel(const float* __restrict__ xyz, const float* __restrict__ feat)
{
    int sk = blockIdx.x*256 + threadIdx.x;   // 0..4095
    int c  = blockIdx.y;                     // 0..290
    int b  = blockIdx.z;
    int id = g_idx[b*SK + sk];
    float val;
    if (c < 3) {
        int s = sk >> 4;
        val = (xyz[((long)b*N_ + id)*3 + c] - g_newxyz[(b*S_+s)*3 + c]) / 0.3f;
    } else {
        val = feat[((long)b*C_ + (c-3))*N_ + id];
    }
    g_h0[((long)b*CIN0 + c)*SK + sk] = val;
}

// ---------------- weight transpose: Wt[c][o] ----------------
__global__ void wt_kernel(const float* __restrict__ W0, const float* __restrict__ W1,
                          const float* __restrict__ W2)
{
    int l = blockIdx.y;
    int Cin = (l == 0) ? CIN0 : C_;
    int e = blockIdx.x*256 + threadIdx.x;
    if (e >= C_*Cin) return;
    const float* W = (l == 0) ? W0 : ((l == 1) ? W1 : W2);
    g_Wt[l*WT_STRIDE + (e % Cin)*C_ + (e / Cin)] = W[e];
}

// ---------------- GEMM + BN + ReLU (+ fused max over k for last layer) ----------------
__device__ __forceinline__ unsigned long long ffma2(unsigned long long a,
                                                    unsigned long long b,
                                                    unsigned long long c)
{
    unsigned long long d;
    asm("fma.rn.f32x2 %0, %1, %2, %3;" : "=l"(d) : "l"(a), "l"(b), "l"(c));
    return d;
}

__global__ void __launch_bounds__(256) mlp_kernel(int in_sel, int layer, int out_sel,
    const float* __restrict__ gg, const float* __restrict__ bbp,
    const float* __restrict__ mmp, const float* __restrict__ vvp,
    float* __restrict__ out_ptr, int Cin)
{
    __shared__ float As[16][128];   // A duplicated into (w,w) pairs
    __shared__ float Bs[16][128];

    const float* in = (in_sel == 0) ? g_h0 : ((in_sel == 1) ? g_h1 : g_h2);
    float* out = (out_sel == 1) ? g_h1 : ((out_sel == 2) ? g_h2 : out_ptr);
    const float* Wt = g_Wt + layer*WT_STRIDE;

    int b  = blockIdx.z;
    int m0 = blockIdx.y * 64;
    int n0 = blockIdx.x * 128;
    int tid = threadIdx.x, tx = tid & 15, ty = tid >> 4;
    const float* inb = in + (long)b*Cin*SK;

    unsigned long long acc[4][4];
#pragma unroll
    for (int i = 0; i < 4; i++)
#pragma unroll
        for (int p = 0; p < 4; p++) acc[i][p] = 0ull;

    int a_kk = tid >> 6;    // 0..3 (step 4)
    int a_mm = tid & 63;
    int b_kk = tid >> 7;    // 0..1 (step 2)
    int b_nn = tid & 127;
    int kt_count = (Cin + 15) >> 4;

    for (int kt = 0; kt < kt_count; kt++) {
        int c0 = kt * 16;
#pragma unroll
        for (int p = 0; p < 4; p++) {
            int kk = a_kk + p*4;
            int cc = c0 + kk, m = m0 + a_mm;
            float w = (cc < Cin && m < C_) ? Wt[cc*C_ + m] : 0.0f;
            *(float2*)&As[kk][a_mm*2] = make_float2(w, w);
        }
#pragma unroll
        for (int p = 0; p < 8; p++) {
            int kk = b_kk + p*2;
            int cc = c0 + kk;
            Bs[kk][b_nn] = (cc < Cin) ? inb[(long)cc*SK + n0 + b_nn] : 0.0f;
        }
        __syncthreads();
#pragma unroll
        for (int kk = 0; kk < 16; kk++) {
            ulonglong2 A0 = *(ulonglong2*)&As[kk][ty*8];
            ulonglong2 A1 = *(ulonglong2*)&As[kk][ty*8 + 4];
            ulonglong2 B0 = *(ulonglong2*)&Bs[kk][tx*8];
            ulonglong2 B1 = *(ulonglong2*)&Bs[kk][tx*8 + 4];
            acc[0][0] = ffma2(A0.x, B0.x, acc[0][0]);
            acc[0][1] = ffma2(A0.x, B0.y, acc[0][1]);
            acc[0][2] = ffma2(A0.x, B1.x, acc[0][2]);
            acc[0][3] = ffma2(A0.x, B1.y, acc[0][3]);
            acc[1][0] = ffma2(A0.y, B0.x, acc[1][0]);
            acc[1][1] = ffma2(A0.y, B0.y, acc[1][1]);
            acc[1][2] = ffma2(A0.y, B1.x, acc[1][2]);
            acc[1][3] = ffma2(A0.y, B1.y, acc[1][3]);
            acc[2][0] = ffma2(A1.x, B0.x, acc[2][0]);
            acc[2][1] = ffma2(A1.x, B0.y, acc[2][1]);
            acc[2][2] = ffma2(A1.x, B1.x, acc[2][2]);
            acc[2][3] = ffma2(A1.x, B1.y, acc[2][3]);
            acc[3][0] = ffma2(A1.y, B0.x, acc[3][0]);
            acc[3][1] = ffma2(A1.y, B0.y, acc[3][1]);
            acc[3][2] = ffma2(A1.y, B1.x, acc[3][2]);
            acc[3][3] = ffma2(A1.y, B1.y, acc[3][3]);
        }
        __syncthreads();
    }

    // epilogue: BN + ReLU (+ optional fused max over nsample=16)
#pragma unroll
    for (int i = 0; i < 4; i++) {
        int o = m0 + ty*4 + i;
        bool valid = (o < C_);
        float sc = 0.0f, sh = 0.0f;
        if (valid) {
            sc = gg[o] * rsqrtf(vvp[o] + 1e-5f);
            sh = bbp[o] - mmp[o]*sc;
        }
        float r[8];
#pragma unroll
        for (int p = 0; p < 4; p++) {
            float lo, hi;
            asm("mov.b64 {%0,%1}, %2;" : "=f"(lo), "=f"(hi) : "l"(acc[i][p]));
            r[2*p]   = fmaxf(lo*sc + sh, 0.0f);
            r[2*p+1] = fmaxf(hi*sc + sh, 0.0f);
        }
        if (out_sel != 0) {
            if (valid) {
                float* dst = out + ((long)b*C_ + o)*SK + n0 + tx*8;
                *(float4*)dst       = make_float4(r[0], r[1], r[2], r[3]);
                *(float4*)(dst + 4) = make_float4(r[4], r[5], r[6], r[7]);
            }
        } else {
            float mx = r[0];
#pragma unroll
            for (int j = 1; j < 8; j++) mx = fmaxf(mx, r[j]);
            float om = __shfl_xor_sync(0xffffffffu, mx, 1);
            mx = fmaxf(mx, om);
            if (valid && ((tx & 1) == 0)) {
                out[((long)b*C_ + o)*S_ + ((n0 + tx*8) >> 4)] = mx;
            }
        }
    }
}

// ---------------- launch ----------------
extern "C" void kernel_launch(void* const* d_in, const int* in_sizes, int n_in,
                              void* d_out, int out_size)
{
    const float* xyz  = (const float*)d_in[0];
    const float* feat = (const float*)d_in[1];
    const float* W0 = (const float*)d_in[2];
    const float* g0 = (const float*)d_in[3];
    const float* b0 = (const float*)d_in[4];
    const float* m0 = (const float*)d_in[5];
    const float* v0 = (const float*)d_in[6];
    const float* W1 = (const float*)d_in[7];
    const float* g1 = (const float*)d_in[8];
    const float* b1 = (const float*)d_in[9];
    const float* m1 = (const float*)d_in[10];
    const float* v1 = (const float*)d_in[11];
    const float* W2 = (const float*)d_in[12];
    const float* g2 = (const float*)d_in[13];
    const float* b2 = (const float*)d_in[14];
    const float* m2 = (const float*)d_in[15];
    const float* v2 = (const float*)d_in[16];

    float* out      = (float*)d_out;
    float* out_xyz  = out;                               // (B,S,3)
    float* out_feat = out + B_*S_*3;                     // (B,C,S)
    float* out_inds = out + B_*S_*3 + (long)B_*C_*S_;    // (B,S) as float

    cudaFuncSetAttribute(fps_kernel, cudaFuncAttributeMaxDynamicSharedMemorySize,
                         3*N_*(int)sizeof(float));

    wt_kernel<<<dim3(328, 3), 256>>>(W0, W1, W2);
    fps_kernel<<<B_, 1024, 3*N_*sizeof(float)>>>(xyz, out_xyz, out_inds);
    ballq_kernel<<<512, 256>>>(xyz);
    gather_kernel<<<dim3(16, CIN0, B_), 256>>>(xyz, feat);
    mlp_kernel<<<dim3(32, 5, B_), 256>>>(0, 0, 1, g0, b0, m0, v0, nullptr, CIN0);
    mlp_kernel<<<dim3(32, 5, B_), 256>>>(1, 1, 2, g1, b1, m1, v1, nullptr, C_);
    mlp_kernel<<<dim3(32, 5, B_), 256>>>(2, 2, 0, g2, b2, m2, v2, out_feat, C_);
}

// round 4
// speedup vs baseline: 1.8230x; 1.8230x over previous
#include <cuda_runtime.h>
#include <cuda_bf16.h>
#include <cstdint>

#define B_   16
#define N_   16384
#define C_   288
#define S_   256
#define KS   16
#define CIN0 291
#define SK4  4096
#define KPAD 320
#define MPAD 384
#define KT_  5
#define MLP_SMEM (131072 + 1024)

// ---------------- scratch ----------------
__device__ float g_newxyz[B_*S_*3];
__device__ int   g_idx[B_*S_*KS];
__device__ __align__(256) __nv_bfloat16 g_aHi[(size_t)B_*SK4*KPAD];
__device__ __align__(256) __nv_bfloat16 g_aLo[(size_t)B_*SK4*KPAD];
__device__ __align__(256) __nv_bfloat16 g_bHi[(size_t)B_*SK4*KPAD];
__device__ __align__(256) __nv_bfloat16 g_bLo[(size_t)B_*SK4*KPAD];
__device__ __align__(256) __nv_bfloat16 g_wHi[3*MPAD*KPAD];
__device__ __align__(256) __nv_bfloat16 g_wLo[3*MPAD*KPAD];

// ---------------- helpers ----------------
__device__ __forceinline__ uint32_t smem_u32(const void* p) {
    uint32_t a;
    asm("{ .reg .u64 t; cvta.to.shared.u64 t, %1; cvt.u32.u64 %0, t; }" : "=r"(a) : "l"(p));
    return a;
}
#define CP_COMMIT() asm volatile("cp.async.commit_group;" ::: "memory")
#define CP_WAIT(n)  asm volatile("cp.async.wait_group %0;" :: "n"(n) : "memory")
__device__ __forceinline__ void cp16(uint32_t s, const void* g) {
    asm volatile("cp.async.cg.shared.global [%0], [%1], 16;" :: "r"(s), "l"(g) : "memory");
}
__device__ __forceinline__ void ldsm4(uint32_t* r, uint32_t a) {
    asm volatile("ldmatrix.sync.aligned.m8n8.x4.shared.b16 {%0,%1,%2,%3}, [%4];"
        : "=r"(r[0]),"=r"(r[1]),"=r"(r[2]),"=r"(r[3]) : "r"(a));
}
__device__ __forceinline__ void ldsm2(uint32_t* r, uint32_t a) {
    asm volatile("ldmatrix.sync.aligned.m8n8.x2.shared.b16 {%0,%1}, [%2];"
        : "=r"(r[0]),"=r"(r[1]) : "r"(a));
}
__device__ __forceinline__ void mma16816(float* c, const uint32_t* a, const uint32_t* b) {
    asm volatile("mma.sync.aligned.m16n8k16.row.col.f32.bf16.bf16.f32 "
        "{%0,%1,%2,%3}, {%4,%5,%6,%7}, {%8,%9}, {%0,%1,%2,%3};"
        : "+f"(c[0]),"+f"(c[1]),"+f"(c[2]),"+f"(c[3])
        : "r"(a[0]),"r"(a[1]),"r"(a[2]),"r"(a[3]), "r"(b[0]),"r"(b[1]));
}
__device__ __forceinline__ uint32_t sw128(uint32_t off) {
    return off ^ ((off >> 3) & 0x70);
}

// ---------------- FPS (bit-exact, as passing R1) ----------------
extern __shared__ float fps_sm[];
__global__ void __launch_bounds__(1024) fps_kernel(const float* __restrict__ xyz,
                                                   float* __restrict__ out_xyz,
                                                   float* __restrict__ out_inds)
{
    float* sx = fps_sm;
    float* sy = fps_sm + N_;
    float* sz = fps_sm + 2*N_;
    __shared__ float r_d[32];
    __shared__ int   r_i[32];
    __shared__ float s_c[3];
    __shared__ int   s_ci;

    int b = blockIdx.x, tid = threadIdx.x;
    const float* xb = xyz + (long)b*N_*3;
    for (int i = tid; i < N_; i += 1024) {
        sx[i] = xb[3*i];
        sy[i] = xb[3*i+1];
        sz[i] = xb[3*i+2];
    }
    float dist[16];
#pragma unroll
    for (int j = 0; j < 16; j++) dist[j] = 1e10f;
    if (tid == 0) s_ci = 0;
    __syncthreads();
    if (tid == 0) { s_c[0] = sx[0]; s_c[1] = sy[0]; s_c[2] = sz[0]; }
    __syncthreads();

    int lane = tid & 31, wid = tid >> 5;
    for (int t = 0; t < S_; t++) {
        float cx = s_c[0], cy = s_c[1], cz = s_c[2];
        if (tid == 0) {
            int ci = s_ci;
            out_inds[b*S_ + t] = (float)ci;
            out_xyz[(b*S_ + t)*3 + 0] = cx;
            out_xyz[(b*S_ + t)*3 + 1] = cy;
            out_xyz[(b*S_ + t)*3 + 2] = cz;
            g_newxyz[(b*S_ + t)*3 + 0] = cx;
            g_newxyz[(b*S_ + t)*3 + 1] = cy;
            g_newxyz[(b*S_ + t)*3 + 2] = cz;
        }
        float bd = -1.0f; int bi = 0;
#pragma unroll
        for (int j = 0; j < 16; j++) {
            int p = j*1024 + tid;
            float dx = sx[p] - cx, dy = sy[p] - cy, dz = sz[p] - cz;
            float d = __fadd_rn(__fadd_rn(__fmul_rn(dx,dx), __fmul_rn(dy,dy)), __fmul_rn(dz,dz));
            float dm = fminf(dist[j], d);
            dist[j] = dm;
            if (dm > bd) { bd = dm; bi = p; }
        }
#pragma unroll
        for (int off = 16; off; off >>= 1) {
            float od = __shfl_down_sync(0xffffffffu, bd, off);
            int   oi = __shfl_down_sync(0xffffffffu, bi, off);
            if (od > bd || (od == bd && oi < bi)) { bd = od; bi = oi; }
        }
        if (lane == 0) { r_d[wid] = bd; r_i[wid] = bi; }
        __syncthreads();
        if (wid == 0) {
            bd = r_d[lane]; bi = r_i[lane];
#pragma unroll
            for (int off = 16; off; off >>= 1) {
                float od = __shfl_down_sync(0xffffffffu, bd, off);
                int   oi = __shfl_down_sync(0xffffffffu, bi, off);
                if (od > bd || (od == bd && oi < bi)) { bd = od; bi = oi; }
            }
            if (lane == 0) { s_ci = bi; s_c[0] = sx[bi]; s_c[1] = sy[bi]; s_c[2] = sz[bi]; }
        }
        __syncthreads();
    }
}

// ---------------- ball query ----------------
__global__ void ballq_kernel(const float* __restrict__ xyz)
{
    int gw   = (blockIdx.x * blockDim.x + threadIdx.x) >> 5;
    int lane = threadIdx.x & 31;
    int b = gw >> 8, s = gw & 255;
    const float* xb = xyz + (long)b*N_*3;
    float cx = g_newxyz[(b*S_+s)*3 + 0];
    float cy = g_newxyz[(b*S_+s)*3 + 1];
    float cz = g_newxyz[(b*S_+s)*3 + 2];
    int* out = g_idx + (b*S_+s)*KS;
    int count = 0, first = -1;
    for (int base = 0; base < N_; base += 32) {
        int p = base + lane;
        float dx = xb[3*p] - cx, dy = xb[3*p+1] - cy, dz = xb[3*p+2] - cz;
        float d = __fadd_rn(__fadd_rn(__fmul_rn(dx,dx), __fmul_rn(dy,dy)), __fmul_rn(dz,dz));
        bool in = d < 0.09f;
        unsigned mask = __ballot_sync(0xffffffffu, in);
        if (first < 0 && mask) first = base + __ffs(mask) - 1;
        if (in) {
            int slot = count + __popc(mask & ((1u << lane) - 1u));
            if (slot < KS) out[slot] = p;
        }
        count += __popc(mask);
        if (count >= KS) break;
    }
    if (lane < KS && lane >= count) out[lane] = first;
}

// ---------------- gather -> act A [n][k] bf16 hi/lo, zero-padded K ----------------
__global__ void gather_kernel(const float* __restrict__ xyz, const float* __restrict__ feat)
{
    int w    = (blockIdx.x * blockDim.x + threadIdx.x) >> 5;
    int lane = threadIdx.x & 31;
    int b = w >> 12, n = w & 4095;
    int id = g_idx[b*SK4 + n];
    int s = n >> 4;
    size_t orow = ((size_t)b*SK4 + n) * KPAD;
    for (int c = lane; c < KPAD; c += 32) {
        float val = 0.0f;
        if (c < 3) {
            val = (xyz[((size_t)b*N_ + id)*3 + c] - g_newxyz[(b*S_+s)*3 + c]) / 0.3f;
        } else if (c < CIN0) {
            val = feat[((size_t)b*C_ + (c-3))*N_ + id];
        }
        __nv_bfloat16 h = __float2bfloat16_rn(val);
        __nv_bfloat16 l = __float2bfloat16_rn(val - __bfloat162float(h));
        g_aHi[orow + c] = h;
        g_aLo[orow + c] = l;
    }
}

// ---------------- weight prep ----------------
__global__ void wprep_kernel(const float* __restrict__ W0, const float* __restrict__ W1,
                             const float* __restrict__ W2)
{
    int i = blockIdx.x*256 + threadIdx.x;
    if (i >= 3*MPAD*KPAD) return;
    int l = i / (MPAD*KPAD);
    int r = i % (MPAD*KPAD);
    int m = r / KPAD, k = r % KPAD;
    int cin = (l == 0) ? CIN0 : C_;
    float w = 0.0f;
    if (m < C_ && k < cin) {
        const float* W = (l == 0) ? W0 : ((l == 1) ? W1 : W2);
        w = W[m*cin + k];
    }
    __nv_bfloat16 h = __float2bfloat16_rn(w);
    __nv_bfloat16 lo = __float2bfloat16_rn(w - __bfloat162float(h));
    g_wHi[i] = h;
    g_wLo[i] = lo;
}

// ---------------- mma.sync bf16 GEMM (3-term split) + BN/ReLU (+max) ----------------
// grid (32 ntiles, 3 mtiles, 16 batches), 256 threads (8 warps, 2m x 4n of 64x32)
__global__ void __launch_bounds__(256, 1) mlp_mma(
    const __nv_bfloat16* __restrict__ Whi, const __nv_bfloat16* __restrict__ Wlo,
    const __nv_bfloat16* __restrict__ Xhi, const __nv_bfloat16* __restrict__ Xlo,
    __nv_bfloat16* __restrict__ Ohi, __nv_bfloat16* __restrict__ Olo,
    float* __restrict__ Omax,
    const float* __restrict__ gg, const float* __restrict__ bbp,
    const float* __restrict__ mmp, const float* __restrict__ vvp, int maxmode)
{
    extern __shared__ char dsm_raw[];
    __shared__ float s_sc[128], s_sh[128];

    uint32_t raw = smem_u32(dsm_raw);
    uint32_t dsm = (raw + 1023u) & ~1023u;
    char* dptr = dsm_raw + (dsm - raw);

    int tid = threadIdx.x, lane = tid & 31, wid = tid >> 5;
    int wm = wid & 1, wn = wid >> 1;
    int n0 = blockIdx.x * 128, m0 = blockIdx.y * 128, b = blockIdx.z;

    if (tid < 128) {
        int o = m0 + tid;
        float sc = 0.0f, sh = 0.0f;
        if (o < C_) {
            sc = gg[o] * rsqrtf(vvp[o] + 1e-5f);
            sh = bbp[o] - mmp[o]*sc;
        }
        s_sc[tid] = sc; s_sh[tid] = sh;
    }

    const char* aHsrc = (const char*)(Whi + (size_t)m0 * KPAD);
    const char* aLsrc = (const char*)(Wlo + (size_t)m0 * KPAD);
    const char* bHsrc = (const char*)(Xhi + ((size_t)b*SK4 + n0) * KPAD);
    const char* bLsrc = (const char*)(Xlo + ((size_t)b*SK4 + n0) * KPAD);

    auto load_stage = [&](int kt, int s) {
        uint32_t sb = dsm + s*65536;
        int k0b = kt * 128;
        const char* srcs[4] = { aHsrc, aLsrc, bHsrc, bLsrc };
#pragma unroll
        for (int t = 0; t < 4; t++) {
            uint32_t tb = sb + t*16384;
            const char* g = srcs[t] + k0b;
#pragma unroll
            for (int i = 0; i < 4; i++) {
                int idx = tid + i*256;
                int r = idx >> 3, c = idx & 7;
                cp16(tb + sw128(r*128 + c*16), g + (size_t)r*(KPAD*2) + c*16);
            }
        }
        CP_COMMIT();
    };

    load_stage(0, 0);
    load_stage(1, 1);

    float acc[4][4][4];
#pragma unroll
    for (int i = 0; i < 4; i++)
#pragma unroll
        for (int j = 0; j < 4; j++)
#pragma unroll
            for (int r = 0; r < 4; r++) acc[i][j][r] = 0.0f;

    // per-thread static fragment offsets (pre-swizzle, k part added later)
    uint32_t aoff[4], boff[4];
#pragma unroll
    for (int i = 0; i < 4; i++)
        aoff[i] = (wm*64 + i*16 + (lane & 15))*128 + (lane >> 4)*16;
#pragma unroll
    for (int j = 0; j < 4; j++)
        boff[j] = (wn*32 + j*8 + (lane & 7))*128 + ((lane >> 3) & 1)*16;

    __syncthreads();  // s_sc ready (also pre-loop)

    for (int kt = 0; kt < KT_; kt++) {
        int s = kt & 1;
        if (kt + 1 < KT_) CP_WAIT(1); else CP_WAIT(0);
        __syncthreads();
        uint32_t sb = dsm + s*65536;
        uint32_t tAh = sb, tAl = sb + 16384, tBh = sb + 32768, tBl = sb + 49152;
#pragma unroll
        for (int ks = 0; ks < 4; ks++) {
            uint32_t ah[4][4], al[4][4], bh[4][2], bl[4][2];
#pragma unroll
            for (int i = 0; i < 4; i++) {
                uint32_t o = sw128(aoff[i] + ks*32);
                ldsm4(ah[i], tAh + o);
                ldsm4(al[i], tAl + o);
            }
#pragma unroll
            for (int j = 0; j < 4; j++) {
                uint32_t o = sw128(boff[j] + ks*32);
                ldsm2(bh[j], tBh + o);
                ldsm2(bl[j], tBl + o);
            }
#pragma unroll
            for (int i = 0; i < 4; i++)
#pragma unroll
                for (int j = 0; j < 4; j++) {
                    mma16816(acc[i][j], ah[i], bh[j]);
                    mma16816(acc[i][j], ah[i], bl[j]);
                    mma16816(acc[i][j], al[i], bh[j]);
                }
        }
        if (kt + 2 < KT_) {
            __syncthreads();
            load_stage(kt + 2, s);
        }
    }

    // ---------------- epilogue ----------------
    if (maxmode) {
#pragma unroll
        for (int i = 0; i < 4; i++) {
#pragma unroll
            for (int r = 0; r < 2; r++) {
                int ml = wm*64 + i*16 + (lane >> 2) + r*8;
                float sc = s_sc[ml], sh = s_sh[ml];
#pragma unroll
                for (int g = 0; g < 2; g++) {
                    float mx = 0.0f;
#pragma unroll
                    for (int jj = 0; jj < 2; jj++) {
                        int j = g*2 + jj;
                        float v0 = fmaxf(fmaf(acc[i][j][r*2],   sc, sh), 0.0f);
                        float v1 = fmaxf(fmaf(acc[i][j][r*2+1], sc, sh), 0.0f);
                        mx = fmaxf(mx, fmaxf(v0, v1));
                    }
                    mx = fmaxf(mx, __shfl_xor_sync(0xffffffffu, mx, 1));
                    mx = fmaxf(mx, __shfl_xor_sync(0xffffffffu, mx, 2));
                    int o = m0 + ml;
                    if ((lane & 3) == 0 && o < C_) {
                        int sgrp = (n0 >> 4) + wn*2 + g;
                        Omax[((size_t)b*C_ + o)*S_ + sgrp] = mx;
                    }
                }
            }
        }
    } else {
        __syncthreads();   // stages no longer needed; reuse as transpose buffer
        float* smt = (float*)dptr;   // [m][n] 128x128 floats
#pragma unroll
        for (int i = 0; i < 4; i++) {
#pragma unroll
            for (int r = 0; r < 2; r++) {
                int ml = wm*64 + i*16 + (lane >> 2) + r*8;
                float sc = s_sc[ml], sh = s_sh[ml];
#pragma unroll
                for (int j = 0; j < 4; j++) {
                    int nl = wn*32 + j*8 + (lane & 3)*2;
                    float v0 = fmaxf(fmaf(acc[i][j][r*2],   sc, sh), 0.0f);
                    float v1 = fmaxf(fmaf(acc[i][j][r*2+1], sc, sh), 0.0f);
                    *(float2*)&smt[ml*128 + nl] = make_float2(v0, v1);
                }
            }
        }
        __syncthreads();
        int n = tid >> 1, half = tid & 1;
        int colbase = m0 + half*64;
        if (colbase < KPAD) {
            size_t doff = ((size_t)b*SK4 + n0 + n)*KPAD + colbase;
#pragma unroll
            for (int cc = 0; cc < 64; cc += 8) {
                uint32_t h4[4], l4[4];
#pragma unroll
                for (int e = 0; e < 4; e++) {
                    float v0 = smt[(half*64 + cc + 2*e)*128 + n];
                    float v1 = smt[(half*64 + cc + 2*e + 1)*128 + n];
                    __nv_bfloat16 h0 = __float2bfloat16_rn(v0);
                    __nv_bfloat16 h1 = __float2bfloat16_rn(v1);
                    __nv_bfloat16 l0 = __float2bfloat16_rn(v0 - __bfloat162float(h0));
                    __nv_bfloat16 l1 = __float2bfloat16_rn(v1 - __bfloat162float(h1));
                    h4[e] = (uint32_t)__bfloat16_as_ushort(h0) | ((uint32_t)__bfloat16_as_ushort(h1) << 16);
                    l4[e] = (uint32_t)__bfloat16_as_ushort(l0) | ((uint32_t)__bfloat16_as_ushort(l1) << 16);
                }
                *(uint4*)(Ohi + doff + cc) = make_uint4(h4[0], h4[1], h4[2], h4[3]);
                *(uint4*)(Olo + doff + cc) = make_uint4(l4[0], l4[1], l4[2], l4[3]);
            }
        }
    }
}

// ---------------- launch ----------------
extern "C" void kernel_launch(void* const* d_in, const int* in_sizes, int n_in,
                              void* d_out, int out_size)
{
    const float* xyz  = (const float*)d_in[0];
    const float* feat = (const float*)d_in[1];
    const float* W0 = (const float*)d_in[2];
    const float* g0 = (const float*)d_in[3];
    const float* b0 = (const float*)d_in[4];
    const float* m0 = (const float*)d_in[5];
    const float* v0 = (const float*)d_in[6];
    const float* W1 = (const float*)d_in[7];
    const float* g1 = (const float*)d_in[8];
    const float* b1 = (const float*)d_in[9];
    const float* m1 = (const float*)d_in[10];
    const float* v1 = (const float*)d_in[11];
    const float* W2 = (const float*)d_in[12];
    const float* g2 = (const float*)d_in[13];
    const float* b2 = (const float*)d_in[14];
    const float* m2 = (const float*)d_in[15];
    const float* v2 = (const float*)d_in[16];

    float* out      = (float*)d_out;
    float* out_xyz  = out;
    float* out_feat = out + B_*S_*3;
    float* out_inds = out + B_*S_*3 + (long)B_*C_*S_;

    cudaFuncSetAttribute(fps_kernel, cudaFuncAttributeMaxDynamicSharedMemorySize,
                         3*N_*(int)sizeof(float));
    cudaFuncSetAttribute(mlp_mma, cudaFuncAttributeMaxDynamicSharedMemorySize, MLP_SMEM);

    wprep_kernel<<<(3*MPAD*KPAD + 255)/256, 256>>>(W0, W1, W2);
    fps_kernel<<<B_, 1024, 3*N_*sizeof(float)>>>(xyz, out_xyz, out_inds);
    ballq_kernel<<<512, 256>>>(xyz);
    gather_kernel<<<8192, 256>>>(xyz, feat);

    __nv_bfloat16 *wh, *wl, *ah, *al, *bh, *bl;
    cudaGetSymbolAddress((void**)&wh, g_wHi);
    cudaGetSymbolAddress((void**)&wl, g_wLo);
    cudaGetSymbolAddress((void**)&ah, g_aHi);
    cudaGetSymbolAddress((void**)&al, g_aLo);
    cudaGetSymbolAddress((void**)&bh, g_bHi);
    cudaGetSymbolAddress((void**)&bl, g_bLo);

    dim3 grid(32, 3, 16);
    const int L = MPAD*KPAD;
    mlp_mma<<<grid, 256, MLP_SMEM>>>(wh,       wl,       ah, al, bh, bl, nullptr,
                                     g0, b0, m0, v0, 0);
    mlp_mma<<<grid, 256, MLP_SMEM>>>(wh + L,   wl + L,   bh, bl, ah, al, nullptr,
                                     g1, b1, m1, v1, 0);
    mlp_mma<<<grid, 256, MLP_SMEM>>>(wh + 2*L, wl + 2*L, ah, al, nullptr, nullptr, out_feat,
                                     g2, b2, m2, v2, 1);
}